// round 11
// baseline (speedup 1.0000x reference)
#include <cuda_runtime.h>
#include <cuda_bf16.h>
#include <cuda_pipeline.h>
#include <mma.h>
#include <math.h>

using namespace nvcuda;

// Problem constants
#define B_  2
#define S_  2048
#define D_  1024
#define H_  16
#define DK_ 64
#define M_  (B_*S_)

// GEMM v2 tiling (measured ~104us per GEMM)
#define BM 128
#define BN 128
#define BK 32
#define LDT 40
#define TILE_ELEMS (BM*LDT)
#define STAGE_ELEMS (4*TILE_ELEMS)
#define SMEM_BYTES (2*STAGE_ELEMS*2)

// Flash v4 smem layout (bytes). bf16 tiles stride 72 elems (144B); f32 stride 72.
#define FQH 0
#define FQL 18432
#define FKV0 36864
#define FKV1 73728
#define FS  110592
#define FPH 147456
#define FPL 165888
#define FST 184320
#define FLASH_SMEM 185856

// Scratch (device globals — no allocation allowed)
__device__ __nv_bfloat16 g_Xh[M_*D_];
__device__ __nv_bfloat16 g_Xl[M_*D_];
__device__ __nv_bfloat16 g_Wh[D_*D_];
__device__ __nv_bfloat16 g_Wl[D_*D_];
__device__ __nv_bfloat16 g_Qh[M_*D_];
__device__ __nv_bfloat16 g_Ql[M_*D_];
__device__ __nv_bfloat16 g_Kh[M_*D_];
__device__ __nv_bfloat16 g_Kl[M_*D_];
__device__ __nv_bfloat16 g_Vh[M_*D_];
__device__ __nv_bfloat16 g_Vl[M_*D_];

// ---------------------------------------------------------------------------
// fp32 -> (hi, lo) bf16 split helpers.
// ---------------------------------------------------------------------------
__device__ __forceinline__ void split4(const float4* src, __nv_bfloat16* hi,
                                       __nv_bfloat16* lo, int i)
{
    float4 v = src[i];
    __nv_bfloat16 h0 = __float2bfloat16(v.x);
    __nv_bfloat16 h1 = __float2bfloat16(v.y);
    __nv_bfloat16 h2 = __float2bfloat16(v.z);
    __nv_bfloat16 h3 = __float2bfloat16(v.w);
    __nv_bfloat162 hh0, hh1, ll0, ll1;
    hh0.x = h0; hh0.y = h1; hh1.x = h2; hh1.y = h3;
    ll0.x = __float2bfloat16(v.x - __bfloat162float(h0));
    ll0.y = __float2bfloat16(v.y - __bfloat162float(h1));
    ll1.x = __float2bfloat16(v.z - __bfloat162float(h2));
    ll1.y = __float2bfloat16(v.w - __bfloat162float(h3));
    *(__nv_bfloat162*)&hi[i*4]     = hh0;
    *(__nv_bfloat162*)&hi[i*4 + 2] = hh1;
    *(__nv_bfloat162*)&lo[i*4]     = ll0;
    *(__nv_bfloat162*)&lo[i*4 + 2] = ll1;
}

__global__ __launch_bounds__(256)
void cvt_merged_kernel(const float4* __restrict__ x,
                       __nv_bfloat16* __restrict__ xh,
                       __nv_bfloat16* __restrict__ xl,
                       int nx4,
                       const float4* __restrict__ w,
                       __nv_bfloat16* __restrict__ wh,
                       __nv_bfloat16* __restrict__ wl,
                       int nw4)
{
    int i = blockIdx.x * blockDim.x + threadIdx.x;
    if (i < nx4) {
        split4(x, xh, xl, i);
    } else if (i < nx4 + nw4) {
        split4(w, wh, wl, i - nx4);
    }
}

// ---------------------------------------------------------------------------
// GEMM v2 + optional split epilogue:
//   split=0: Y = X@W^T + bias (fp32)
//   split=1: write hi/lo bf16 of the result to Yh/Yl (via smem staging)
// ---------------------------------------------------------------------------
__global__ __launch_bounds__(256)
void gemm_wmma_kernel(const __nv_bfloat16* __restrict__ Xh,
                      const __nv_bfloat16* __restrict__ Xl,
                      const __nv_bfloat16* __restrict__ Wh,
                      const __nv_bfloat16* __restrict__ Wl,
                      const float* __restrict__ bias,
                      float* __restrict__ Y,
                      __nv_bfloat16* __restrict__ Yh,
                      __nv_bfloat16* __restrict__ Yl,
                      int split,
                      int M, int N, int K)
{
    extern __shared__ __nv_bfloat16 sm[];
    __shared__ __align__(16) float biasTile[16][136];

    const int tid = threadIdx.x;
    const int wid = tid >> 5;
    const int m0  = blockIdx.y * BM;
    const int n0  = blockIdx.x * BN;
    const int wm  = (wid & 1) * 64;
    const int wn  = (wid >> 1) * 32;

    for (int idx = tid; idx < 16 * 128; idx += 256) {
        int r = idx >> 7;
        int c = idx & 127;
        biasTile[r][c] = bias[n0 + c];
    }
    __syncthreads();

    wmma::fragment<wmma::accumulator, 16, 16, 16, float> acc[4][2];
    for (int mi = 0; mi < 4; mi++)
        for (int ni = 0; ni < 2; ni++)
            wmma::load_matrix_sync(acc[mi][ni], &biasTile[0][wn + ni * 16], 136,
                                   wmma::mem_row_major);

    const int NT = K / BK;

    {
        for (int p = 0; p < 2; p++) {
            int chunk = tid + p * 256;
            int row = chunk >> 2;
            int cc  = chunk & 3;
            const __nv_bfloat16* sa = Xh + (size_t)(m0 + row) * K + cc * 8;
            const __nv_bfloat16* sb = Xl + (size_t)(m0 + row) * K + cc * 8;
            const __nv_bfloat16* sc = Wh + (size_t)(n0 + row) * K + cc * 8;
            const __nv_bfloat16* sd = Wl + (size_t)(n0 + row) * K + cc * 8;
            int so = row * LDT + cc * 8;
            __pipeline_memcpy_async(&sm[so], sa, 16);
            __pipeline_memcpy_async(&sm[TILE_ELEMS + so], sb, 16);
            __pipeline_memcpy_async(&sm[2 * TILE_ELEMS + so], sc, 16);
            __pipeline_memcpy_async(&sm[3 * TILE_ELEMS + so], sd, 16);
        }
        __pipeline_commit();
    }

    for (int t = 0; t < NT; t++) {
        int st = (t & 1) * STAGE_ELEMS;
        if (t + 1 < NT) {
            int k0 = (t + 1) * BK;
            int sn = ((t + 1) & 1) * STAGE_ELEMS;
            for (int p = 0; p < 2; p++) {
                int chunk = tid + p * 256;
                int row = chunk >> 2;
                int cc  = chunk & 3;
                const __nv_bfloat16* sa = Xh + (size_t)(m0 + row) * K + k0 + cc * 8;
                const __nv_bfloat16* sb = Xl + (size_t)(m0 + row) * K + k0 + cc * 8;
                const __nv_bfloat16* sc = Wh + (size_t)(n0 + row) * K + k0 + cc * 8;
                const __nv_bfloat16* sd = Wl + (size_t)(n0 + row) * K + k0 + cc * 8;
                int so = row * LDT + cc * 8;
                __pipeline_memcpy_async(&sm[sn + so], sa, 16);
                __pipeline_memcpy_async(&sm[sn + TILE_ELEMS + so], sb, 16);
                __pipeline_memcpy_async(&sm[sn + 2 * TILE_ELEMS + so], sc, 16);
                __pipeline_memcpy_async(&sm[sn + 3 * TILE_ELEMS + so], sd, 16);
            }
            __pipeline_commit();
            __pipeline_wait_prior(1);
        } else {
            __pipeline_wait_prior(0);
        }
        __syncthreads();

        for (int ks = 0; ks < 2; ks++) {
            int kc = ks * 16;
            wmma::fragment<wmma::matrix_a, 16, 16, 16, __nv_bfloat16, wmma::row_major> ah[4], al[4];
            wmma::fragment<wmma::matrix_b, 16, 16, 16, __nv_bfloat16, wmma::col_major> bh[2], bl[2];
            for (int mi = 0; mi < 4; mi++) {
                int r = wm + mi * 16;
                wmma::load_matrix_sync(ah[mi], &sm[st + r * LDT + kc], LDT);
                wmma::load_matrix_sync(al[mi], &sm[st + TILE_ELEMS + r * LDT + kc], LDT);
            }
            for (int ni = 0; ni < 2; ni++) {
                int r = wn + ni * 16;
                wmma::load_matrix_sync(bh[ni], &sm[st + 2 * TILE_ELEMS + r * LDT + kc], LDT);
                wmma::load_matrix_sync(bl[ni], &sm[st + 3 * TILE_ELEMS + r * LDT + kc], LDT);
            }
            for (int mi = 0; mi < 4; mi++) {
                for (int ni = 0; ni < 2; ni++) {
                    wmma::mma_sync(acc[mi][ni], ah[mi], bh[ni], acc[mi][ni]);
                    wmma::mma_sync(acc[mi][ni], ah[mi], bl[ni], acc[mi][ni]);
                    wmma::mma_sync(acc[mi][ni], al[mi], bh[ni], acc[mi][ni]);
                }
            }
        }
        __syncthreads();
    }

    if (split == 0) {
        for (int mi = 0; mi < 4; mi++) {
            for (int ni = 0; ni < 2; ni++) {
                int row = m0 + wm + mi * 16;
                int col = n0 + wn + ni * 16;
                wmma::store_matrix_sync(&Y[(size_t)row * N + col], acc[mi][ni], N,
                                        wmma::mem_row_major);
            }
        }
    } else {
        // Stage fp32 result in smem (free after main loop), then split to bf16.
        float* stage = (float*)sm;   // 128 x 132 stride = 67.6 KB
        for (int mi = 0; mi < 4; mi++)
            for (int ni = 0; ni < 2; ni++)
                wmma::store_matrix_sync(stage + (wm + mi * 16) * 132 + wn + ni * 16,
                                        acc[mi][ni], 132, wmma::mem_row_major);
        __syncthreads();
        for (int idx = tid; idx < 128 * 128; idx += 256) {
            int r = idx >> 7;
            int c = idx & 127;
            float v = stage[r * 132 + c];
            __nv_bfloat16 hv = __float2bfloat16(v);
            size_t g = (size_t)(m0 + r) * N + n0 + c;
            Yh[g] = hv;
            Yl[g] = __float2bfloat16(v - __bfloat162float(hv));
        }
    }
}

// ---------------------------------------------------------------------------
// Flash v4 (causal, tensor-core): 128 queries/CTA, O accumulators in
// registers (rescaled in-register via f32 acc fragment row map), 3 syncs/tile.
// Writes O directly as hi/lo bf16.
// ---------------------------------------------------------------------------
__device__ __forceinline__ void flash_load_q(char* dst, const __nv_bfloat16* src,
                                             int rowbase, int h, int tid)
{
    for (int p = 0; p < 4; p++) {
        int idx = tid + p * 256;     // 0..1023
        int r = idx >> 3;            // 0..127
        int c = idx & 7;
        const __nv_bfloat16* s = src + (size_t)(rowbase + r) * D_ + h * DK_ + c * 8;
        __pipeline_memcpy_async(dst + r * 144 + c * 16, s, 16);
    }
}

__device__ __forceinline__ void flash_load_kv(char* dst, const __nv_bfloat16* src,
                                              int rowbase, int h, int tid)
{
    for (int p = 0; p < 2; p++) {
        int idx = tid + p * 256;     // 0..511
        int r = idx >> 3;            // 0..63
        int c = idx & 7;
        const __nv_bfloat16* s = src + (size_t)(rowbase + r) * D_ + h * DK_ + c * 8;
        __pipeline_memcpy_async(dst + r * 144 + c * 16, s, 16);
    }
}

// Scale f32 accumulator fragment rows: elements {0,1,4,5} -> row lane/4,
// {2,3,6,7} -> row lane/4 + 8 (sm_80+ layout).
__device__ __forceinline__ void scale_frag_rows(
    wmma::fragment<wmma::accumulator, 16, 16, 16, float>& f, float s0, float s1)
{
    f.x[0] *= s0; f.x[1] *= s0; f.x[4] *= s0; f.x[5] *= s0;
    f.x[2] *= s1; f.x[3] *= s1; f.x[6] *= s1; f.x[7] *= s1;
}

__global__ __launch_bounds__(256)
void flash_wmma_kernel(const __nv_bfloat16* __restrict__ Qh_g,
                       const __nv_bfloat16* __restrict__ Ql_g,
                       const __nv_bfloat16* __restrict__ Kh_g,
                       const __nv_bfloat16* __restrict__ Kl_g,
                       const __nv_bfloat16* __restrict__ Vh_g,
                       const __nv_bfloat16* __restrict__ Vl_g,
                       __nv_bfloat16* __restrict__ Oh_g,
                       __nv_bfloat16* __restrict__ Ol_g)
{
    extern __shared__ char smb[];

    const int tid = threadIdx.x;
    const int wid = tid >> 5;
    const int lane = tid & 31;
    const int qt  = blockIdx.x;          // 0..15
    const int bh  = blockIdx.y;          // 0..31
    const int b   = bh / H_;
    const int h   = bh % H_;
    const int q0  = qt * 128;

    float* Sbuf  = (float*)(smb + FS);
    float* mArr  = (float*)(smb + FST);
    float* lArr  = mArr + 128;
    float* scArr = lArr + 128;

    // Q (hi/lo) + KV tile 0 — one commit group.
    flash_load_q(smb + FQH, Qh_g, b * S_ + q0, h, tid);
    flash_load_q(smb + FQL, Ql_g, b * S_ + q0, h, tid);
    {
        char* kv = smb + FKV0;
        flash_load_kv(kv,         Kh_g, b * S_, h, tid);
        flash_load_kv(kv + 9216,  Kl_g, b * S_, h, tid);
        flash_load_kv(kv + 18432, Vh_g, b * S_, h, tid);
        flash_load_kv(kv + 27648, Vl_g, b * S_, h, tid);
    }
    __pipeline_commit();

    if (tid < 128) {
        mArr[tid] = -INFINITY;
        lArr[tid] = 0.f;
    }

    const int wq = wid * 16;             // warp's 16 q-rows
    const int rowA = wq + (lane >> 2);   // fragment row (first half)
    const int rowB = rowA + 8;           // fragment row (second half)

    wmma::fragment<wmma::accumulator, 16, 16, 16, float> o[4];
    for (int ni = 0; ni < 4; ni++) wmma::fill_fragment(o[ni], 0.f);

    const int ntiles = 2 * qt + 2;
    for (int kt = 0; kt < ntiles; kt++) {
        __pipeline_wait_prior(0);
        __syncthreads();                 // tile kt visible; prev iter done
        if (kt + 1 < ntiles) {
            char* kv = smb + (((kt + 1) & 1) ? FKV1 : FKV0);
            int kb2 = b * S_ + (kt + 1) * 64;
            flash_load_kv(kv,         Kh_g, kb2, h, tid);
            flash_load_kv(kv + 9216,  Kl_g, kb2, h, tid);
            flash_load_kv(kv + 18432, Vh_g, kb2, h, tid);
            flash_load_kv(kv + 27648, Vl_g, kb2, h, tid);
            __pipeline_commit();
        }

        const char* kv = smb + ((kt & 1) ? FKV1 : FKV0);
        const __nv_bfloat16* Khs = (const __nv_bfloat16*)kv;
        const __nv_bfloat16* Kls = (const __nv_bfloat16*)(kv + 9216);
        const __nv_bfloat16* Vhs = (const __nv_bfloat16*)(kv + 18432);
        const __nv_bfloat16* Vls = (const __nv_bfloat16*)(kv + 27648);
        const __nv_bfloat16* Qhs = (const __nv_bfloat16*)(smb + FQH);
        const __nv_bfloat16* Qls = (const __nv_bfloat16*)(smb + FQL);

        // ---- S = Q K^T : each warp computes 16 q-rows x 64 keys ----
        {
            wmma::fragment<wmma::accumulator, 16, 16, 16, float> s[4];
            for (int ni = 0; ni < 4; ni++) wmma::fill_fragment(s[ni], 0.f);
            for (int ks = 0; ks < 4; ks++) {
                int kc = ks * 16;
                wmma::fragment<wmma::matrix_a, 16, 16, 16, __nv_bfloat16, wmma::row_major> qh, ql;
                wmma::load_matrix_sync(qh, Qhs + wq * 72 + kc, 72);
                wmma::load_matrix_sync(ql, Qls + wq * 72 + kc, 72);
                for (int ni = 0; ni < 4; ni++) {
                    wmma::fragment<wmma::matrix_b, 16, 16, 16, __nv_bfloat16, wmma::col_major> kh, kl;
                    wmma::load_matrix_sync(kh, Khs + (ni * 16) * 72 + kc, 72);
                    wmma::load_matrix_sync(kl, Kls + (ni * 16) * 72 + kc, 72);
                    wmma::mma_sync(s[ni], qh, kh, s[ni]);
                    wmma::mma_sync(s[ni], qh, kl, s[ni]);
                    wmma::mma_sync(s[ni], ql, kh, s[ni]);
                }
            }
            for (int ni = 0; ni < 4; ni++)
                wmma::store_matrix_sync(Sbuf + wq * 72 + ni * 16, s[ni], 72,
                                        wmma::mem_row_major);
        }
        __syncthreads();

        // ---- online softmax: 2 threads per row, 32 cols each ----
        {
            const int r  = tid >> 1;
            const int cb = (tid & 1) * 32;
            const int kb = kt * 64;
            float* Srow = Sbuf + r * 72 + cb;
            float mx = -INFINITY;
            for (int i = 0; i < 32; i++) {
                float v = Srow[i] * 0.125f;
                if (kb + cb + i > q0 + r) v = -1e9f;
                Srow[i] = v;
                mx = fmaxf(mx, v);
            }
            mx = fmaxf(mx, __shfl_xor_sync(0xffffffffu, mx, 1));
            float mold = mArr[r];
            __syncwarp();
            float mnew = fmaxf(mold, mx);
            float sum = 0.f;
            __nv_bfloat16* Phs = (__nv_bfloat16*)(smb + FPH);
            __nv_bfloat16* Pls = (__nv_bfloat16*)(smb + FPL);
            for (int i = 0; i < 32; i += 2) {
                float p0 = __expf(Srow[i] - mnew);
                float p1 = __expf(Srow[i + 1] - mnew);
                sum += p0 + p1;
                __nv_bfloat16 h0 = __float2bfloat16(p0);
                __nv_bfloat16 h1 = __float2bfloat16(p1);
                __nv_bfloat162 hh, ll;
                hh.x = h0; hh.y = h1;
                ll.x = __float2bfloat16(p0 - __bfloat162float(h0));
                ll.y = __float2bfloat16(p1 - __bfloat162float(h1));
                *(__nv_bfloat162*)&Phs[r * 72 + cb + i] = hh;
                *(__nv_bfloat162*)&Pls[r * 72 + cb + i] = ll;
            }
            sum += __shfl_xor_sync(0xffffffffu, sum, 1);
            float sc = __expf(mold - mnew);
            if ((tid & 1) == 0) {
                mArr[r] = mnew;
                lArr[r] = lArr[r] * sc + sum;
                scArr[r] = sc;
            }
        }
        __syncthreads();

        // ---- rescale O in registers, then O += P V ----
        {
            float s0 = scArr[rowA];
            float s1 = scArr[rowB];
            for (int ni = 0; ni < 4; ni++) scale_frag_rows(o[ni], s0, s1);

            const __nv_bfloat16* Phs = (const __nv_bfloat16*)(smb + FPH);
            const __nv_bfloat16* Pls = (const __nv_bfloat16*)(smb + FPL);
            for (int ks = 0; ks < 4; ks++) {
                int kc = ks * 16;
                wmma::fragment<wmma::matrix_a, 16, 16, 16, __nv_bfloat16, wmma::row_major> ph, pl;
                wmma::load_matrix_sync(ph, Phs + wq * 72 + kc, 72);
                wmma::load_matrix_sync(pl, Pls + wq * 72 + kc, 72);
                for (int ni = 0; ni < 4; ni++) {
                    wmma::fragment<wmma::matrix_b, 16, 16, 16, __nv_bfloat16, wmma::row_major> vh, vl;
                    wmma::load_matrix_sync(vh, Vhs + kc * 72 + ni * 16, 72);
                    wmma::load_matrix_sync(vl, Vls + kc * 72 + ni * 16, 72);
                    wmma::mma_sync(o[ni], ph, vh, o[ni]);
                    wmma::mma_sync(o[ni], ph, vl, o[ni]);
                    wmma::mma_sync(o[ni], pl, vh, o[ni]);
                }
            }
        }
    }

    // ---- epilogue: normalize, stage to smem, split to hi/lo bf16 global ----
    {
        float i0 = 1.f / lArr[rowA];
        float i1 = 1.f / lArr[rowB];
        for (int ni = 0; ni < 4; ni++) scale_frag_rows(o[ni], i0, i1);
        for (int ni = 0; ni < 4; ni++)
            wmma::store_matrix_sync(Sbuf + wq * 72 + ni * 16, o[ni], 72,
                                    wmma::mem_row_major);
    }
    __syncthreads();
    for (int idx = tid; idx < 128 * 64; idx += 256) {
        int r = idx >> 6;
        int c = idx & 63;
        float v = Sbuf[r * 72 + c];
        __nv_bfloat16 hv = __float2bfloat16(v);
        size_t g = (size_t)(b * S_ + q0 + r) * D_ + h * DK_ + c;
        Oh_g[g] = hv;
        Ol_g[g] = __float2bfloat16(v - __bfloat162float(hv));
    }
}

// ---------------------------------------------------------------------------
// Launch. Inputs: q,k,v,mask,Wq,bq,Wk,bk,Wv,bv,Wo,bo
// ---------------------------------------------------------------------------
extern "C" void kernel_launch(void* const* d_in, const int* in_sizes, int n_in,
                              void* d_out, int out_size)
{
    const float* q    = (const float*)d_in[0];
    const float* k    = (const float*)d_in[1];
    const float* v    = (const float*)d_in[2];
    const float* Wq   = (const float*)d_in[4];
    const float* bq   = (const float*)d_in[5];
    const float* Wk   = (const float*)d_in[6];
    const float* bk   = (const float*)d_in[7];
    const float* Wv   = (const float*)d_in[8];
    const float* bv   = (const float*)d_in[9];
    const float* Wo   = (const float*)d_in[10];
    const float* bo   = (const float*)d_in[11];
    float* out = (float*)d_out;

    __nv_bfloat16 *Xh; __nv_bfloat16 *Xl; __nv_bfloat16 *Wh; __nv_bfloat16 *Wl;
    __nv_bfloat16 *Qh; __nv_bfloat16 *Ql; __nv_bfloat16 *Kh; __nv_bfloat16 *Kl;
    __nv_bfloat16 *Vh; __nv_bfloat16 *Vl;
    cudaGetSymbolAddress((void**)&Xh, g_Xh);
    cudaGetSymbolAddress((void**)&Xl, g_Xl);
    cudaGetSymbolAddress((void**)&Wh, g_Wh);
    cudaGetSymbolAddress((void**)&Wl, g_Wl);
    cudaGetSymbolAddress((void**)&Qh, g_Qh);
    cudaGetSymbolAddress((void**)&Ql, g_Ql);
    cudaGetSymbolAddress((void**)&Kh, g_Kh);
    cudaGetSymbolAddress((void**)&Kl, g_Kl);
    cudaGetSymbolAddress((void**)&Vh, g_Vh);
    cudaGetSymbolAddress((void**)&Vl, g_Vl);

    cudaFuncSetAttribute(gemm_wmma_kernel,
                         cudaFuncAttributeMaxDynamicSharedMemorySize, SMEM_BYTES);
    cudaFuncSetAttribute(flash_wmma_kernel,
                         cudaFuncAttributeMaxDynamicSharedMemorySize, FLASH_SMEM);

    const int nX4 = M_ * D_ / 4;
    const int nW4 = D_ * D_ / 4;
    dim3 cvtg((nX4 + nW4 + 255) / 256);
    dim3 cvtw((nW4 + 255) / 256);
    dim3 ggrid(D_ / BN, M_ / BM);

    // Projections: GEMM writes hi/lo bf16 directly.
    cvt_merged_kernel<<<cvtg, 256>>>((const float4*)q, Xh, Xl, nX4,
                                     (const float4*)Wq, Wh, Wl, nW4);
    gemm_wmma_kernel<<<ggrid, 256, SMEM_BYTES>>>(Xh, Xl, Wh, Wl, bq, out,
                                                 Qh, Ql, 1, M_, D_, D_);
    cvt_merged_kernel<<<cvtg, 256>>>((const float4*)k, Xh, Xl, nX4,
                                     (const float4*)Wk, Wh, Wl, nW4);
    gemm_wmma_kernel<<<ggrid, 256, SMEM_BYTES>>>(Xh, Xl, Wh, Wl, bk, out,
                                                 Kh, Kl, 1, M_, D_, D_);
    cvt_merged_kernel<<<cvtg, 256>>>((const float4*)v, Xh, Xl, nX4,
                                     (const float4*)Wv, Wh, Wl, nW4);
    gemm_wmma_kernel<<<ggrid, 256, SMEM_BYTES>>>(Xh, Xl, Wh, Wl, bv, out,
                                                 Vh, Vl, 1, M_, D_, D_);

    // Attention: writes O hi/lo into g_Xh/g_Xl (input of the final GEMM).
    dim3 fgrid(S_ / 128, B_ * H_);   // (16, 32)
    flash_wmma_kernel<<<fgrid, 256, FLASH_SMEM>>>(Qh, Ql, Kh, Kl, Vh, Vl, Xh, Xl);

    // Output projection: W-only convert, fp32 output.
    cvt_merged_kernel<<<cvtw, 256>>>((const float4*)q, Xh, Xl, 0,
                                     (const float4*)Wo, Wh, Wl, nW4);
    gemm_wmma_kernel<<<ggrid, 256, SMEM_BYTES>>>(Xh, Xl, Wh, Wl, bo, out,
                                                 Qh, Ql, 0, M_, D_, D_);
}

// round 12
// speedup vs baseline: 1.1157x; 1.1157x over previous
#include <cuda_runtime.h>
#include <cuda_bf16.h>
#include <cuda_pipeline.h>
#include <mma.h>
#include <math.h>

using namespace nvcuda;

// Problem constants
#define B_  2
#define S_  2048
#define D_  1024
#define H_  16
#define DK_ 64
#define M_  (B_*S_)

// GEMM v2 tiling (measured ~105us per GEMM, 2 CTAs/SM)
#define BM 128
#define BN 128
#define BK 32
#define LDT 40
#define TILE_ELEMS (BM*LDT)
#define STAGE_ELEMS (4*TILE_ELEMS)
#define SMEM_BYTES (2*STAGE_ELEMS*2)

// Flash v5 smem layout (bytes): 64 queries, single KV buffer -> ~93KB, 2 CTAs/SM.
#define FQH 0
#define FQL 9216
#define FKV 18432            // Kh, Kl, Vh, Vl each 9216 -> ends 55296
#define FS  55296            // 64 x 72 f32 = 18432 -> ends 73728
#define FPH 73728
#define FPL 82944
#define FST 92160            // m[64], l[64], sc[64]
#define FLASH_SMEM 92928

// Scratch (device globals — no allocation allowed)
__device__ __nv_bfloat16 g_Xh[M_*D_];
__device__ __nv_bfloat16 g_Xl[M_*D_];
__device__ __nv_bfloat16 g_Wh[D_*D_];
__device__ __nv_bfloat16 g_Wl[D_*D_];
__device__ __nv_bfloat16 g_Qh[M_*D_];
__device__ __nv_bfloat16 g_Ql[M_*D_];
__device__ __nv_bfloat16 g_Kh[M_*D_];
__device__ __nv_bfloat16 g_Kl[M_*D_];
__device__ __nv_bfloat16 g_Vh[M_*D_];
__device__ __nv_bfloat16 g_Vl[M_*D_];

// ---------------------------------------------------------------------------
// fp32 -> (hi, lo) bf16 split helpers.
// ---------------------------------------------------------------------------
__device__ __forceinline__ void split4(const float4* src, __nv_bfloat16* hi,
                                       __nv_bfloat16* lo, int i)
{
    float4 v = src[i];
    __nv_bfloat16 h0 = __float2bfloat16(v.x);
    __nv_bfloat16 h1 = __float2bfloat16(v.y);
    __nv_bfloat16 h2 = __float2bfloat16(v.z);
    __nv_bfloat16 h3 = __float2bfloat16(v.w);
    __nv_bfloat162 hh0, hh1, ll0, ll1;
    hh0.x = h0; hh0.y = h1; hh1.x = h2; hh1.y = h3;
    ll0.x = __float2bfloat16(v.x - __bfloat162float(h0));
    ll0.y = __float2bfloat16(v.y - __bfloat162float(h1));
    ll1.x = __float2bfloat16(v.z - __bfloat162float(h2));
    ll1.y = __float2bfloat16(v.w - __bfloat162float(h3));
    *(__nv_bfloat162*)&hi[i*4]     = hh0;
    *(__nv_bfloat162*)&hi[i*4 + 2] = hh1;
    *(__nv_bfloat162*)&lo[i*4]     = ll0;
    *(__nv_bfloat162*)&lo[i*4 + 2] = ll1;
}

__global__ __launch_bounds__(256)
void cvt_merged_kernel(const float4* __restrict__ x,
                       __nv_bfloat16* __restrict__ xh,
                       __nv_bfloat16* __restrict__ xl,
                       int nx4,
                       const float4* __restrict__ w,
                       __nv_bfloat16* __restrict__ wh,
                       __nv_bfloat16* __restrict__ wl,
                       int nw4)
{
    int i = blockIdx.x * blockDim.x + threadIdx.x;
    if (i < nx4) {
        split4(x, xh, xl, i);
    } else if (i < nx4 + nw4) {
        split4(w, wh, wl, i - nx4);
    }
}

// ---------------------------------------------------------------------------
// GEMM v2 + optional split epilogue (unchanged from R11).
// ---------------------------------------------------------------------------
__global__ __launch_bounds__(256)
void gemm_wmma_kernel(const __nv_bfloat16* __restrict__ Xh,
                      const __nv_bfloat16* __restrict__ Xl,
                      const __nv_bfloat16* __restrict__ Wh,
                      const __nv_bfloat16* __restrict__ Wl,
                      const float* __restrict__ bias,
                      float* __restrict__ Y,
                      __nv_bfloat16* __restrict__ Yh,
                      __nv_bfloat16* __restrict__ Yl,
                      int split,
                      int M, int N, int K)
{
    extern __shared__ __nv_bfloat16 sm[];
    __shared__ __align__(16) float biasTile[16][136];

    const int tid = threadIdx.x;
    const int wid = tid >> 5;
    const int m0  = blockIdx.y * BM;
    const int n0  = blockIdx.x * BN;
    const int wm  = (wid & 1) * 64;
    const int wn  = (wid >> 1) * 32;

    for (int idx = tid; idx < 16 * 128; idx += 256) {
        int r = idx >> 7;
        int c = idx & 127;
        biasTile[r][c] = bias[n0 + c];
    }
    __syncthreads();

    wmma::fragment<wmma::accumulator, 16, 16, 16, float> acc[4][2];
    for (int mi = 0; mi < 4; mi++)
        for (int ni = 0; ni < 2; ni++)
            wmma::load_matrix_sync(acc[mi][ni], &biasTile[0][wn + ni * 16], 136,
                                   wmma::mem_row_major);

    const int NT = K / BK;

    {
        for (int p = 0; p < 2; p++) {
            int chunk = tid + p * 256;
            int row = chunk >> 2;
            int cc  = chunk & 3;
            const __nv_bfloat16* sa = Xh + (size_t)(m0 + row) * K + cc * 8;
            const __nv_bfloat16* sb = Xl + (size_t)(m0 + row) * K + cc * 8;
            const __nv_bfloat16* sc = Wh + (size_t)(n0 + row) * K + cc * 8;
            const __nv_bfloat16* sd = Wl + (size_t)(n0 + row) * K + cc * 8;
            int so = row * LDT + cc * 8;
            __pipeline_memcpy_async(&sm[so], sa, 16);
            __pipeline_memcpy_async(&sm[TILE_ELEMS + so], sb, 16);
            __pipeline_memcpy_async(&sm[2 * TILE_ELEMS + so], sc, 16);
            __pipeline_memcpy_async(&sm[3 * TILE_ELEMS + so], sd, 16);
        }
        __pipeline_commit();
    }

    for (int t = 0; t < NT; t++) {
        int st = (t & 1) * STAGE_ELEMS;
        if (t + 1 < NT) {
            int k0 = (t + 1) * BK;
            int sn = ((t + 1) & 1) * STAGE_ELEMS;
            for (int p = 0; p < 2; p++) {
                int chunk = tid + p * 256;
                int row = chunk >> 2;
                int cc  = chunk & 3;
                const __nv_bfloat16* sa = Xh + (size_t)(m0 + row) * K + k0 + cc * 8;
                const __nv_bfloat16* sb = Xl + (size_t)(m0 + row) * K + k0 + cc * 8;
                const __nv_bfloat16* sc = Wh + (size_t)(n0 + row) * K + k0 + cc * 8;
                const __nv_bfloat16* sd = Wl + (size_t)(n0 + row) * K + k0 + cc * 8;
                int so = row * LDT + cc * 8;
                __pipeline_memcpy_async(&sm[sn + so], sa, 16);
                __pipeline_memcpy_async(&sm[sn + TILE_ELEMS + so], sb, 16);
                __pipeline_memcpy_async(&sm[sn + 2 * TILE_ELEMS + so], sc, 16);
                __pipeline_memcpy_async(&sm[sn + 3 * TILE_ELEMS + so], sd, 16);
            }
            __pipeline_commit();
            __pipeline_wait_prior(1);
        } else {
            __pipeline_wait_prior(0);
        }
        __syncthreads();

        for (int ks = 0; ks < 2; ks++) {
            int kc = ks * 16;
            wmma::fragment<wmma::matrix_a, 16, 16, 16, __nv_bfloat16, wmma::row_major> ah[4], al[4];
            wmma::fragment<wmma::matrix_b, 16, 16, 16, __nv_bfloat16, wmma::col_major> bh[2], bl[2];
            for (int mi = 0; mi < 4; mi++) {
                int r = wm + mi * 16;
                wmma::load_matrix_sync(ah[mi], &sm[st + r * LDT + kc], LDT);
                wmma::load_matrix_sync(al[mi], &sm[st + TILE_ELEMS + r * LDT + kc], LDT);
            }
            for (int ni = 0; ni < 2; ni++) {
                int r = wn + ni * 16;
                wmma::load_matrix_sync(bh[ni], &sm[st + 2 * TILE_ELEMS + r * LDT + kc], LDT);
                wmma::load_matrix_sync(bl[ni], &sm[st + 3 * TILE_ELEMS + r * LDT + kc], LDT);
            }
            for (int mi = 0; mi < 4; mi++) {
                for (int ni = 0; ni < 2; ni++) {
                    wmma::mma_sync(acc[mi][ni], ah[mi], bh[ni], acc[mi][ni]);
                    wmma::mma_sync(acc[mi][ni], ah[mi], bl[ni], acc[mi][ni]);
                    wmma::mma_sync(acc[mi][ni], al[mi], bh[ni], acc[mi][ni]);
                }
            }
        }
        __syncthreads();
    }

    if (split == 0) {
        for (int mi = 0; mi < 4; mi++) {
            for (int ni = 0; ni < 2; ni++) {
                int row = m0 + wm + mi * 16;
                int col = n0 + wn + ni * 16;
                wmma::store_matrix_sync(&Y[(size_t)row * N + col], acc[mi][ni], N,
                                        wmma::mem_row_major);
            }
        }
    } else {
        float* stage = (float*)sm;
        for (int mi = 0; mi < 4; mi++)
            for (int ni = 0; ni < 2; ni++)
                wmma::store_matrix_sync(stage + (wm + mi * 16) * 132 + wn + ni * 16,
                                        acc[mi][ni], 132, wmma::mem_row_major);
        __syncthreads();
        for (int idx = tid; idx < 128 * 128; idx += 256) {
            int r = idx >> 7;
            int c = idx & 127;
            float v = stage[r * 132 + c];
            __nv_bfloat16 hv = __float2bfloat16(v);
            size_t g = (size_t)(m0 + r) * N + n0 + c;
            Yh[g] = hv;
            Yl[g] = __float2bfloat16(v - __bfloat162float(hv));
        }
    }
}

// ---------------------------------------------------------------------------
// Flash v5 (causal, tensor-core): 64 queries/CTA, single-buffered KV,
// register O accumulators (validated row map), ~93KB smem -> 2 CTAs/SM.
// Warp w: q-rows (w&3)*16, dims/keys (w>>2)*32. Writes O as hi/lo bf16.
// ---------------------------------------------------------------------------
__device__ __forceinline__ void flash_load_64(char* dst, const __nv_bfloat16* src,
                                              int rowbase, int h, int tid)
{
    for (int p = 0; p < 2; p++) {
        int idx = tid + p * 256;     // 0..511
        int r = idx >> 3;            // 0..63
        int c = idx & 7;
        const __nv_bfloat16* s = src + (size_t)(rowbase + r) * D_ + h * DK_ + c * 8;
        __pipeline_memcpy_async(dst + r * 144 + c * 16, s, 16);
    }
}

// Scale f32 accumulator fragment rows (sm_80+ layout, validated R11):
// elements {0,1,4,5} -> row lane/4, {2,3,6,7} -> row lane/4 + 8.
__device__ __forceinline__ void scale_frag_rows(
    wmma::fragment<wmma::accumulator, 16, 16, 16, float>& f, float s0, float s1)
{
    f.x[0] *= s0; f.x[1] *= s0; f.x[4] *= s0; f.x[5] *= s0;
    f.x[2] *= s1; f.x[3] *= s1; f.x[6] *= s1; f.x[7] *= s1;
}

__global__ __launch_bounds__(256)
void flash_wmma_kernel(const __nv_bfloat16* __restrict__ Qh_g,
                       const __nv_bfloat16* __restrict__ Ql_g,
                       const __nv_bfloat16* __restrict__ Kh_g,
                       const __nv_bfloat16* __restrict__ Kl_g,
                       const __nv_bfloat16* __restrict__ Vh_g,
                       const __nv_bfloat16* __restrict__ Vl_g,
                       __nv_bfloat16* __restrict__ Oh_g,
                       __nv_bfloat16* __restrict__ Ol_g)
{
    extern __shared__ char smb[];

    const int tid  = threadIdx.x;
    const int wid  = tid >> 5;
    const int lane = tid & 31;
    const int qt   = blockIdx.x;          // 0..31
    const int bhv  = blockIdx.y;          // 0..31
    const int b    = bhv / H_;
    const int h    = bhv % H_;
    const int q0   = qt * 64;

    float* Sbuf  = (float*)(smb + FS);
    float* mArr  = (float*)(smb + FST);
    float* lArr  = mArr + 64;
    float* scArr = lArr + 64;

    // Prologue: Q (hi/lo) + KV tile 0.
    flash_load_64(smb + FQH, Qh_g, b * S_ + q0, h, tid);
    flash_load_64(smb + FQL, Ql_g, b * S_ + q0, h, tid);
    {
        char* kv = smb + FKV;
        flash_load_64(kv,         Kh_g, b * S_, h, tid);
        flash_load_64(kv + 9216,  Kl_g, b * S_, h, tid);
        flash_load_64(kv + 18432, Vh_g, b * S_, h, tid);
        flash_load_64(kv + 27648, Vl_g, b * S_, h, tid);
    }
    __pipeline_commit();

    if (tid < 64) {
        mArr[tid] = -INFINITY;
        lArr[tid] = 0.f;
    }

    const int qr   = (wid & 3) * 16;      // warp q-row base
    const int dc   = (wid >> 2) * 32;     // warp key/dim base
    const int rowA = qr + (lane >> 2);
    const int rowB = rowA + 8;

    wmma::fragment<wmma::accumulator, 16, 16, 16, float> o[2];
    wmma::fill_fragment(o[0], 0.f);
    wmma::fill_fragment(o[1], 0.f);

    const __nv_bfloat16* Qhs = (const __nv_bfloat16*)(smb + FQH);
    const __nv_bfloat16* Qls = (const __nv_bfloat16*)(smb + FQL);
    const __nv_bfloat16* Khs = (const __nv_bfloat16*)(smb + FKV);
    const __nv_bfloat16* Kls = (const __nv_bfloat16*)(smb + FKV + 9216);
    const __nv_bfloat16* Vhs = (const __nv_bfloat16*)(smb + FKV + 18432);
    const __nv_bfloat16* Vls = (const __nv_bfloat16*)(smb + FKV + 27648);
    __nv_bfloat16* Phs = (__nv_bfloat16*)(smb + FPH);
    __nv_bfloat16* Pls = (__nv_bfloat16*)(smb + FPL);

    const int ntiles = qt + 1;
    for (int kt = 0; kt < ntiles; kt++) {
        if (kt > 0) {
            __syncthreads();             // everyone done reading previous KV
            char* kv = smb + FKV;
            int kb2 = b * S_ + kt * 64;
            flash_load_64(kv,         Kh_g, kb2, h, tid);
            flash_load_64(kv + 9216,  Kl_g, kb2, h, tid);
            flash_load_64(kv + 18432, Vh_g, kb2, h, tid);
            flash_load_64(kv + 27648, Vl_g, kb2, h, tid);
            __pipeline_commit();
        }
        __pipeline_wait_prior(0);
        __syncthreads();                 // KV tile kt visible

        // ---- S = Q K^T : warp -> 16 q-rows x 32 keys ----
        {
            wmma::fragment<wmma::accumulator, 16, 16, 16, float> s[2];
            wmma::fill_fragment(s[0], 0.f);
            wmma::fill_fragment(s[1], 0.f);
            for (int ks = 0; ks < 4; ks++) {
                int kc = ks * 16;
                wmma::fragment<wmma::matrix_a, 16, 16, 16, __nv_bfloat16, wmma::row_major> qh, ql;
                wmma::load_matrix_sync(qh, Qhs + qr * 72 + kc, 72);
                wmma::load_matrix_sync(ql, Qls + qr * 72 + kc, 72);
                for (int ni = 0; ni < 2; ni++) {
                    wmma::fragment<wmma::matrix_b, 16, 16, 16, __nv_bfloat16, wmma::col_major> kh, kl;
                    wmma::load_matrix_sync(kh, Khs + (dc + ni * 16) * 72 + kc, 72);
                    wmma::load_matrix_sync(kl, Kls + (dc + ni * 16) * 72 + kc, 72);
                    wmma::mma_sync(s[ni], qh, kh, s[ni]);
                    wmma::mma_sync(s[ni], qh, kl, s[ni]);
                    wmma::mma_sync(s[ni], ql, kh, s[ni]);
                }
            }
            wmma::store_matrix_sync(Sbuf + qr * 72 + dc,      s[0], 72, wmma::mem_row_major);
            wmma::store_matrix_sync(Sbuf + qr * 72 + dc + 16, s[1], 72, wmma::mem_row_major);
        }
        __syncthreads();

        // ---- online softmax: 4 threads/row, 16 cols each ----
        {
            const int r  = tid >> 2;
            const int sub = tid & 3;
            const int cb = sub * 16;
            const int kb = kt * 64;
            float* Srow = Sbuf + r * 72 + cb;
            float vals[16];
            float mx = -INFINITY;
            for (int i = 0; i < 16; i++) {
                float v = Srow[i] * 0.125f;
                if (kb + cb + i > q0 + r) v = -1e9f;
                vals[i] = v;
                mx = fmaxf(mx, v);
            }
            mx = fmaxf(mx, __shfl_xor_sync(0xffffffffu, mx, 1));
            mx = fmaxf(mx, __shfl_xor_sync(0xffffffffu, mx, 2));
            float mold = mArr[r];
            float mnew = fmaxf(mold, mx);
            float sum = 0.f;
            for (int i = 0; i < 16; i += 2) {
                float p0 = __expf(vals[i] - mnew);
                float p1 = __expf(vals[i + 1] - mnew);
                sum += p0 + p1;
                __nv_bfloat16 h0 = __float2bfloat16(p0);
                __nv_bfloat16 h1 = __float2bfloat16(p1);
                __nv_bfloat162 hh, ll;
                hh.x = h0; hh.y = h1;
                ll.x = __float2bfloat16(p0 - __bfloat162float(h0));
                ll.y = __float2bfloat16(p1 - __bfloat162float(h1));
                *(__nv_bfloat162*)&Phs[r * 72 + cb + i] = hh;
                *(__nv_bfloat162*)&Pls[r * 72 + cb + i] = ll;
            }
            sum += __shfl_xor_sync(0xffffffffu, sum, 1);
            sum += __shfl_xor_sync(0xffffffffu, sum, 2);
            float sc = __expf(mold - mnew);
            if (sub == 0) {
                mArr[r] = mnew;
                lArr[r] = lArr[r] * sc + sum;
                scArr[r] = sc;
            }
        }
        __syncthreads();

        // ---- rescale O in registers, then O += P V (warp: 16 rows x 32 dims) ----
        {
            float s0 = scArr[rowA];
            float s1 = scArr[rowB];
            scale_frag_rows(o[0], s0, s1);
            scale_frag_rows(o[1], s0, s1);
            for (int ks = 0; ks < 4; ks++) {
                int kc = ks * 16;
                wmma::fragment<wmma::matrix_a, 16, 16, 16, __nv_bfloat16, wmma::row_major> ph, pl;
                wmma::load_matrix_sync(ph, Phs + qr * 72 + kc, 72);
                wmma::load_matrix_sync(pl, Pls + qr * 72 + kc, 72);
                for (int ni = 0; ni < 2; ni++) {
                    wmma::fragment<wmma::matrix_b, 16, 16, 16, __nv_bfloat16, wmma::row_major> vh, vl;
                    wmma::load_matrix_sync(vh, Vhs + kc * 72 + dc + ni * 16, 72);
                    wmma::load_matrix_sync(vl, Vls + kc * 72 + dc + ni * 16, 72);
                    wmma::mma_sync(o[ni], ph, vh, o[ni]);
                    wmma::mma_sync(o[ni], ph, vl, o[ni]);
                    wmma::mma_sync(o[ni], pl, vh, o[ni]);
                }
            }
        }
    }

    // ---- epilogue: normalize, stage to smem, split to hi/lo bf16 global ----
    {
        float i0 = 1.f / lArr[rowA];
        float i1 = 1.f / lArr[rowB];
        scale_frag_rows(o[0], i0, i1);
        scale_frag_rows(o[1], i0, i1);
        wmma::store_matrix_sync(Sbuf + qr * 72 + dc,      o[0], 72, wmma::mem_row_major);
        wmma::store_matrix_sync(Sbuf + qr * 72 + dc + 16, o[1], 72, wmma::mem_row_major);
    }
    __syncthreads();
    for (int idx = tid; idx < 64 * 64; idx += 256) {
        int r = idx >> 6;
        int c = idx & 63;
        float v = Sbuf[r * 72 + c];
        __nv_bfloat16 hv = __float2bfloat16(v);
        size_t g = (size_t)(b * S_ + q0 + r) * D_ + h * DK_ + c;
        Oh_g[g] = hv;
        Ol_g[g] = __float2bfloat16(v - __bfloat162float(hv));
    }
}

// ---------------------------------------------------------------------------
// Launch. Inputs: q,k,v,mask,Wq,bq,Wk,bk,Wv,bv,Wo,bo
// ---------------------------------------------------------------------------
extern "C" void kernel_launch(void* const* d_in, const int* in_sizes, int n_in,
                              void* d_out, int out_size)
{
    const float* q    = (const float*)d_in[0];
    const float* k    = (const float*)d_in[1];
    const float* v    = (const float*)d_in[2];
    const float* Wq   = (const float*)d_in[4];
    const float* bq   = (const float*)d_in[5];
    const float* Wk   = (const float*)d_in[6];
    const float* bk   = (const float*)d_in[7];
    const float* Wv   = (const float*)d_in[8];
    const float* bv   = (const float*)d_in[9];
    const float* Wo   = (const float*)d_in[10];
    const float* bo   = (const float*)d_in[11];
    float* out = (float*)d_out;

    __nv_bfloat16 *Xh; __nv_bfloat16 *Xl; __nv_bfloat16 *Wh; __nv_bfloat16 *Wl;
    __nv_bfloat16 *Qh; __nv_bfloat16 *Ql; __nv_bfloat16 *Kh; __nv_bfloat16 *Kl;
    __nv_bfloat16 *Vh; __nv_bfloat16 *Vl;
    cudaGetSymbolAddress((void**)&Xh, g_Xh);
    cudaGetSymbolAddress((void**)&Xl, g_Xl);
    cudaGetSymbolAddress((void**)&Wh, g_Wh);
    cudaGetSymbolAddress((void**)&Wl, g_Wl);
    cudaGetSymbolAddress((void**)&Qh, g_Qh);
    cudaGetSymbolAddress((void**)&Ql, g_Ql);
    cudaGetSymbolAddress((void**)&Kh, g_Kh);
    cudaGetSymbolAddress((void**)&Kl, g_Kl);
    cudaGetSymbolAddress((void**)&Vh, g_Vh);
    cudaGetSymbolAddress((void**)&Vl, g_Vl);

    cudaFuncSetAttribute(gemm_wmma_kernel,
                         cudaFuncAttributeMaxDynamicSharedMemorySize, SMEM_BYTES);
    cudaFuncSetAttribute(flash_wmma_kernel,
                         cudaFuncAttributeMaxDynamicSharedMemorySize, FLASH_SMEM);

    const int nX4 = M_ * D_ / 4;
    const int nW4 = D_ * D_ / 4;
    dim3 cvtg((nX4 + nW4 + 255) / 256);
    dim3 cvtw((nW4 + 255) / 256);
    dim3 ggrid(D_ / BN, M_ / BM);

    // Projections: GEMM writes hi/lo bf16 directly.
    cvt_merged_kernel<<<cvtg, 256>>>((const float4*)q, Xh, Xl, nX4,
                                     (const float4*)Wq, Wh, Wl, nW4);
    gemm_wmma_kernel<<<ggrid, 256, SMEM_BYTES>>>(Xh, Xl, Wh, Wl, bq, out,
                                                 Qh, Ql, 1, M_, D_, D_);
    cvt_merged_kernel<<<cvtg, 256>>>((const float4*)k, Xh, Xl, nX4,
                                     (const float4*)Wk, Wh, Wl, nW4);
    gemm_wmma_kernel<<<ggrid, 256, SMEM_BYTES>>>(Xh, Xl, Wh, Wl, bk, out,
                                                 Kh, Kl, 1, M_, D_, D_);
    cvt_merged_kernel<<<cvtg, 256>>>((const float4*)v, Xh, Xl, nX4,
                                     (const float4*)Wv, Wh, Wl, nW4);
    gemm_wmma_kernel<<<ggrid, 256, SMEM_BYTES>>>(Xh, Xl, Wh, Wl, bv, out,
                                                 Vh, Vl, 1, M_, D_, D_);

    // Attention: writes O hi/lo into g_Xh/g_Xl (input of the final GEMM).
    dim3 fgrid(S_ / 64, B_ * H_);   // (32, 32)
    flash_wmma_kernel<<<fgrid, 256, FLASH_SMEM>>>(Qh, Ql, Kh, Kl, Vh, Vl, Xh, Xl);

    // Output projection: W-only convert, fp32 output.
    cvt_merged_kernel<<<cvtw, 256>>>((const float4*)q, Xh, Xl, 0,
                                     (const float4*)Wo, Wh, Wl, nW4);
    gemm_wmma_kernel<<<ggrid, 256, SMEM_BYTES>>>(Xh, Xl, Wh, Wl, bo, out,
                                                 Qh, Ql, 0, M_, D_, D_);
}